// round 6
// baseline (speedup 1.0000x reference)
#include <cuda_runtime.h>
#include <cstdint>

#define D 128
#define N_MAX 50048   // round up a bit for safety

// Scratch (device globals: allocation-free per harness rules)
__device__ int   g_deg[N_MAX];
__device__ float g_dinv[N_MAX];
__device__ float g_y[(size_t)N_MAX * D];   // y[n] = dinv[n] * (x@W + b)[n]

// ---------------------------------------------------------------------------
// 1) degree init: self-loop contributes 1 to every node
__global__ void k_deg_init(int n) {
    int i = blockIdx.x * blockDim.x + threadIdx.x;
    if (i < n) g_deg[i] = 1;
}

// 2) degree histogram over col  (edge_index is int32: JAX x64-disabled
//    canonicalizes the reference's int64 to int32)
__global__ void k_deg_count(const int* __restrict__ col, int E) {
    int i = blockIdx.x * blockDim.x + threadIdx.x;
    if (i < E) atomicAdd(&g_deg[col[i]], 1);
}

// 3) dinv = rsqrt(deg)   (deg >= 1 always due to self-loops)
__global__ void k_dinv(int n) {
    int i = blockIdx.x * blockDim.x + threadIdx.x;
    if (i < n) g_dinv[i] = rsqrtf((float)g_deg[i]);
}

// ---------------------------------------------------------------------------
// 4) xl = x @ W + b ; y = dinv * xl ; write y to scratch AND d_out (self-loop
//    accumulator init). BM=64 rows, BN=128 (full), BK=64 (two k-chunks).
//    Block: 256 threads = (tx 0..31 over col quads) x (ty 0..7 over 8-row groups)
__global__ __launch_bounds__(256) void k_gemm(const float* __restrict__ x,
                                              const float* __restrict__ Wm,
                                              const float* __restrict__ bias,
                                              float* __restrict__ out, int n) {
    __shared__ float w_s[64][D];   // 32 KB : W[kk..kk+64][0..128]
    __shared__ float x_s[64][64];  // 16 KB : x[rows][kk..kk+64]

    const int tid  = threadIdx.x;
    const int tx   = tid & 31;     // col quad: cols tx*4 .. tx*4+3
    const int ty   = tid >> 5;     // row group: rows ty*8 .. ty*8+7
    const int row0 = blockIdx.x * 64;

    float acc[8][4];
#pragma unroll
    for (int i = 0; i < 8; i++)
#pragma unroll
        for (int j = 0; j < 4; j++) acc[i][j] = 0.0f;

    for (int kk = 0; kk < D; kk += 64) {
        // load W chunk: 64 x 128 floats = 2048 float4 / 256 thr = 8 each
        {
            const float4* W4 = (const float4*)(Wm + (size_t)kk * D);
            float4* ws4 = (float4*)&w_s[0][0];
            for (int i = tid; i < 64 * (D / 4); i += 256) ws4[i] = W4[i];
        }
        // load x chunk: 64 rows x 64 cols = 1024 float4 / 256 thr = 4 each
        {
            for (int i = tid; i < 64 * 16; i += 256) {
                int r = i >> 4, c4 = i & 15;
                float4 v = make_float4(0.f, 0.f, 0.f, 0.f);
                if (row0 + r < n)
                    v = *(const float4*)(x + (size_t)(row0 + r) * D + kk + c4 * 4);
                *(float4*)&x_s[r][c4 * 4] = v;
            }
        }
        __syncthreads();

#pragma unroll 4
        for (int k = 0; k < 64; k++) {
            float4 wv = ((const float4*)&w_s[k][0])[tx];
#pragma unroll
            for (int i = 0; i < 8; i++) {
                float xv = x_s[ty * 8 + i][k];   // warp-uniform broadcast
                acc[i][0] += xv * wv.x;
                acc[i][1] += xv * wv.y;
                acc[i][2] += xv * wv.z;
                acc[i][3] += xv * wv.w;
            }
        }
        __syncthreads();
    }

    // epilogue: +bias, *dinv, write y (scratch) and out (accumulator init)
    float4 bv = ((const float4*)bias)[tx];
#pragma unroll
    for (int i = 0; i < 8; i++) {
        int row = row0 + ty * 8 + i;
        if (row < n) {
            float s = g_dinv[row];
            float4 v;
            v.x = (acc[i][0] + bv.x) * s;
            v.y = (acc[i][1] + bv.y) * s;
            v.z = (acc[i][2] + bv.z) * s;
            v.w = (acc[i][3] + bv.w) * s;
            size_t off = (size_t)row * D + tx * 4;
            *(float4*)(g_y + off) = v;
            *(float4*)(out + off) = v;
        }
    }
}

// ---------------------------------------------------------------------------
// 5) edge scatter: one warp per edge. out[row] += y[col]  (128 f32, one
//    float4 per lane, vector reduction red.global.add.v4.f32)
__global__ __launch_bounds__(256) void k_edge(const int* __restrict__ ei,
                                              int E, float* __restrict__ out) {
    int warp = (int)((blockIdx.x * (long long)blockDim.x + threadIdx.x) >> 5);
    int lane = threadIdx.x & 31;
    if (warp >= E) return;

    int r = ei[warp];       // row (scatter target)
    int c = ei[E + warp];   // col (gather source)

    float4 v = *(const float4*)(g_y + (size_t)c * D + lane * 4);
    float* dst = out + (size_t)r * D + lane * 4;
    asm volatile("red.global.add.v4.f32 [%0], {%1,%2,%3,%4};"
                 :: "l"(dst), "f"(v.x), "f"(v.y), "f"(v.z), "f"(v.w)
                 : "memory");
}

// ---------------------------------------------------------------------------
// 6) out[r] *= dinv[r]
__global__ void k_scale(float* __restrict__ out, int n) {
    int i = blockIdx.x * blockDim.x + threadIdx.x;   // over n*32 float4s
    if (i < n * (D / 4)) {
        int node = i >> 5;
        float s = g_dinv[node];
        float4 v = ((float4*)out)[i];
        v.x *= s; v.y *= s; v.z *= s; v.w *= s;
        ((float4*)out)[i] = v;
    }
}

// ---------------------------------------------------------------------------
extern "C" void kernel_launch(void* const* d_in, const int* in_sizes, int n_in,
                              void* d_out, int out_size) {
    const float* x  = (const float*)d_in[0];
    const int*   ei = (const int*)d_in[1];    // int32 (JAX canonicalized)
    const float* Wm = (const float*)d_in[2];
    const float* b  = (const float*)d_in[3];
    float* out = (float*)d_out;

    const int n = in_sizes[0] / D;       // 50000
    const int E = in_sizes[1] / 2;       // 1,600,000

    k_deg_init <<<(n + 255) / 256, 256>>>(n);
    k_deg_count<<<(E + 255) / 256, 256>>>(ei + E, E);
    k_dinv     <<<(n + 255) / 256, 256>>>(n);
    k_gemm     <<<(n + 63) / 64, 256>>>(x, Wm, b, out, n);
    {
        long long threads = (long long)E * 32;
        int blocks = (int)((threads + 255) / 256);
        k_edge <<<blocks, 256>>>(ei, E, out);
    }
    k_scale    <<<(n * (D / 4) + 255) / 256, 256>>>(out, n);
}

// round 9
// speedup vs baseline: 1.1653x; 1.1653x over previous
#include <cuda_runtime.h>
#include <cstdint>

#define D 128
#define N_MAX 50048
#define E_MAX 1600512

// Scratch (device globals: allocation-free per harness rules)
__device__ int   g_deg[N_MAX];
__device__ int   g_rowcnt[N_MAX];
__device__ int   g_roff[N_MAX + 1];
__device__ int   g_cursor[N_MAX];
__device__ int   g_adj[E_MAX];
__device__ float g_dinv[N_MAX];
__device__ float g_y[(size_t)N_MAX * D];   // y[n] = dinv[n] * (x@W + b)[n]

// ---------------------------------------------------------------------------
// 1) init: self-loop degree 1, row counters 0
__global__ void k_init(int n) {
    int i = blockIdx.x * blockDim.x + threadIdx.x;
    if (i < n) { g_deg[i] = 1; g_rowcnt[i] = 0; }
}

// 2) fused histogram: degree over col, CSR counts over row (one pass over ei)
__global__ void k_hist(const int* __restrict__ ei, int E) {
    int i = blockIdx.x * blockDim.x + threadIdx.x;
    if (i < E) {
        int r = ei[i];
        int c = ei[E + i];
        atomicAdd(&g_deg[c], 1);
        atomicAdd(&g_rowcnt[r], 1);
    }
}

// 3) dinv = rsqrt(deg)   (deg >= 1 due to self-loops)
__global__ void k_dinv(int n) {
    int i = blockIdx.x * blockDim.x + threadIdx.x;
    if (i < n) g_dinv[i] = rsqrtf((float)g_deg[i]);
}

// 4) single-block exclusive scan of g_rowcnt -> g_roff / g_cursor (n = 50000)
__global__ __launch_bounds__(1024) void k_scan(int n) {
    __shared__ int warp_sums[32];
    __shared__ int s_carry;
    const int tid = threadIdx.x, lane = tid & 31, wid = tid >> 5;
    if (tid == 0) s_carry = 0;
    __syncthreads();

    for (int base = 0; base < n; base += 1024) {
        int i = base + tid;
        int v = (i < n) ? g_rowcnt[i] : 0;
        int inc = v;
#pragma unroll
        for (int o = 1; o < 32; o <<= 1) {
            int t = __shfl_up_sync(0xffffffffu, inc, o);
            if (lane >= o) inc += t;
        }
        if (lane == 31) warp_sums[wid] = inc;
        __syncthreads();
        if (wid == 0) {
            int ws = warp_sums[lane];
#pragma unroll
            for (int o = 1; o < 32; o <<= 1) {
                int t = __shfl_up_sync(0xffffffffu, ws, o);
                if (lane >= o) ws += t;
            }
            warp_sums[lane] = ws;
        }
        __syncthreads();
        int warp_excl = (wid == 0) ? 0 : warp_sums[wid - 1];
        int excl = s_carry + warp_excl + inc - v;
        if (i < n) { g_roff[i] = excl; g_cursor[i] = excl; }
        __syncthreads();
        if (tid == 0) s_carry += warp_sums[31];
        __syncthreads();
    }
    if (threadIdx.x == 0) g_roff[n] = s_carry;
}

// 5) CSR fill: adj[cursor[r]++] = c  (order within a row irrelevant: sum)
__global__ void k_fill(const int* __restrict__ ei, int E) {
    int i = blockIdx.x * blockDim.x + threadIdx.x;
    if (i < E) {
        int r = ei[i];
        int c = ei[E + i];
        int pos = atomicAdd(&g_cursor[r], 1);
        g_adj[pos] = c;
    }
}

// ---------------------------------------------------------------------------
// 6) xl = x @ W + b ; y = dinv * xl  (scratch only). BM=64, BN=128, BK=64.
__global__ __launch_bounds__(256) void k_gemm(const float* __restrict__ x,
                                              const float* __restrict__ Wm,
                                              const float* __restrict__ bias,
                                              int n) {
    __shared__ float w_s[64][D];   // 32 KB
    __shared__ float x_s[64][64];  // 16 KB

    const int tid  = threadIdx.x;
    const int tx   = tid & 31;     // col quad
    const int ty   = tid >> 5;     // row group
    const int row0 = blockIdx.x * 64;

    float acc[8][4];
#pragma unroll
    for (int i = 0; i < 8; i++)
#pragma unroll
        for (int j = 0; j < 4; j++) acc[i][j] = 0.0f;

    for (int kk = 0; kk < D; kk += 64) {
        {
            const float4* W4 = (const float4*)(Wm + (size_t)kk * D);
            float4* ws4 = (float4*)&w_s[0][0];
            for (int i = tid; i < 64 * (D / 4); i += 256) ws4[i] = W4[i];
        }
        {
            for (int i = tid; i < 64 * 16; i += 256) {
                int r = i >> 4, c4 = i & 15;
                float4 v = make_float4(0.f, 0.f, 0.f, 0.f);
                if (row0 + r < n)
                    v = *(const float4*)(x + (size_t)(row0 + r) * D + kk + c4 * 4);
                *(float4*)&x_s[r][c4 * 4] = v;
            }
        }
        __syncthreads();

#pragma unroll 4
        for (int k = 0; k < 64; k++) {
            float4 wv = ((const float4*)&w_s[k][0])[tx];
#pragma unroll
            for (int i = 0; i < 8; i++) {
                float xv = x_s[ty * 8 + i][k];
                acc[i][0] += xv * wv.x;
                acc[i][1] += xv * wv.y;
                acc[i][2] += xv * wv.z;
                acc[i][3] += xv * wv.w;
            }
        }
        __syncthreads();
    }

    float4 bv = ((const float4*)bias)[tx];
#pragma unroll
    for (int i = 0; i < 8; i++) {
        int row = row0 + ty * 8 + i;
        if (row < n) {
            float s = g_dinv[row];
            float4 v;
            v.x = (acc[i][0] + bv.x) * s;
            v.y = (acc[i][1] + bv.y) * s;
            v.z = (acc[i][2] + bv.z) * s;
            v.w = (acc[i][3] + bv.w) * s;
            *(float4*)(g_y + (size_t)row * D + tx * 4) = v;
        }
    }
}

// ---------------------------------------------------------------------------
// 7) gather: one warp per node, register accumulation, zero atomics.
//    out[r] = dinv[r] * ( y[r] + sum_{c in adj[r]} y[c] )
__global__ __launch_bounds__(256) void k_gather(float* __restrict__ out, int n) {
    const int node = blockIdx.x * 8 + (threadIdx.x >> 5);
    const int lane = threadIdx.x & 31;
    if (node >= n) return;

    const float4* __restrict__ y4 = (const float4*)g_y;

    float4 a0 = y4[(size_t)node * 32 + lane];   // self-loop term
    float4 a1 = make_float4(0.f, 0.f, 0.f, 0.f);

    const int s = g_roff[node];
    const int e = g_roff[node + 1];

    for (int j = s; j < e; j += 32) {
        int cid = 0;
        if (j + lane < e) cid = g_adj[j + lane];
        const int cnt = min(32, e - j);
        int t = 0;
        for (; t + 4 <= cnt; t += 4) {
            int c0 = __shfl_sync(0xffffffffu, cid, t + 0);
            int c1 = __shfl_sync(0xffffffffu, cid, t + 1);
            int c2 = __shfl_sync(0xffffffffu, cid, t + 2);
            int c3 = __shfl_sync(0xffffffffu, cid, t + 3);
            float4 v0 = y4[(size_t)c0 * 32 + lane];
            float4 v1 = y4[(size_t)c1 * 32 + lane];
            float4 v2 = y4[(size_t)c2 * 32 + lane];
            float4 v3 = y4[(size_t)c3 * 32 + lane];
            a0.x += v0.x; a0.y += v0.y; a0.z += v0.z; a0.w += v0.w;
            a1.x += v1.x; a1.y += v1.y; a1.z += v1.z; a1.w += v1.w;
            a0.x += v2.x; a0.y += v2.y; a0.z += v2.z; a0.w += v2.w;
            a1.x += v3.x; a1.y += v3.y; a1.z += v3.z; a1.w += v3.w;
        }
        for (; t < cnt; t++) {
            int c = __shfl_sync(0xffffffffu, cid, t);
            float4 v = y4[(size_t)c * 32 + lane];
            a0.x += v.x; a0.y += v.y; a0.z += v.z; a0.w += v.w;
        }
    }

    const float sd = g_dinv[node];
    float4 r;
    r.x = (a0.x + a1.x) * sd;
    r.y = (a0.y + a1.y) * sd;
    r.z = (a0.z + a1.z) * sd;
    r.w = (a0.w + a1.w) * sd;
    ((float4*)out)[(size_t)node * 32 + lane] = r;
}

// ---------------------------------------------------------------------------
extern "C" void kernel_launch(void* const* d_in, const int* in_sizes, int n_in,
                              void* d_out, int out_size) {
    const float* x  = (const float*)d_in[0];
    const int*   ei = (const int*)d_in[1];    // int32 (JAX canonicalized)
    const float* Wm = (const float*)d_in[2];
    const float* b  = (const float*)d_in[3];
    float* out = (float*)d_out;

    const int n = in_sizes[0] / D;       // 50000
    const int E = in_sizes[1] / 2;       // 1,600,000

    k_init <<<(n + 255) / 256, 256>>>(n);
    k_hist <<<(E + 255) / 256, 256>>>(ei, E);
    k_dinv <<<(n + 255) / 256, 256>>>(n);
    k_scan <<<1, 1024>>>(n);
    k_fill <<<(E + 255) / 256, 256>>>(ei, E);
    k_gemm <<<(n + 63) / 64, 256>>>(x, Wm, b, n);
    k_gather<<<(n + 7) / 8, 256>>>(out, n);
}

// round 10
// speedup vs baseline: 1.4443x; 1.2394x over previous
#include <cuda_runtime.h>
#include <cstdint>

#define D 128
#define N_MAX 50048
#define E_MAX 1600512
#define NB_MAX 64   // max scan blocks (ceil(50000/1024)=49)

// Scratch (device globals: allocation-free per harness rules)
__device__ int   g_deg[N_MAX];
__device__ int   g_rowcnt[N_MAX];
__device__ int   g_roff[N_MAX + 1];
__device__ int   g_cursor[N_MAX];
__device__ int   g_bsum[NB_MAX];
__device__ int   g_boff[NB_MAX];
__device__ int   g_adj[E_MAX];
__device__ float g_dinv[N_MAX];
__device__ float g_y[(size_t)N_MAX * D];   // y[n] = dinv[n] * (x@W + b)[n]

// ---------------------------------------------------------------------------
// 1) init: self-loop degree 1, row counters 0
__global__ void k_init(int n) {
    int i = blockIdx.x * blockDim.x + threadIdx.x;
    if (i < n) { g_deg[i] = 1; g_rowcnt[i] = 0; }
}

// 2) fused histogram: degree over col, CSR counts over row (one pass over ei)
__global__ void k_hist(const int* __restrict__ ei, int E) {
    int i = blockIdx.x * blockDim.x + threadIdx.x;
    if (i < E) {
        int r = ei[i];
        int c = ei[E + i];
        atomicAdd(&g_deg[c], 1);
        atomicAdd(&g_rowcnt[r], 1);
    }
}

// ---------------------------------------------------------------------------
// 3a) per-block exclusive scan of 1024-element chunks + block sums
__global__ __launch_bounds__(1024) void k_scan_blk(int n) {
    __shared__ int warp_sums[32];
    const int tid = threadIdx.x, lane = tid & 31, wid = tid >> 5;
    const int i = blockIdx.x * 1024 + tid;

    int v = (i < n) ? g_rowcnt[i] : 0;
    int inc = v;
#pragma unroll
    for (int o = 1; o < 32; o <<= 1) {
        int t = __shfl_up_sync(0xffffffffu, inc, o);
        if (lane >= o) inc += t;
    }
    if (lane == 31) warp_sums[wid] = inc;
    __syncthreads();
    if (wid == 0) {
        int ws = warp_sums[lane];
#pragma unroll
        for (int o = 1; o < 32; o <<= 1) {
            int t = __shfl_up_sync(0xffffffffu, ws, o);
            if (lane >= o) ws += t;
        }
        warp_sums[lane] = ws;
    }
    __syncthreads();
    int excl = ((wid == 0) ? 0 : warp_sums[wid - 1]) + inc - v;
    if (i < n) g_roff[i] = excl;
    if (tid == 0) g_bsum[blockIdx.x] = warp_sums[31];
}

// 3b) scan the block sums (nb <= 64, one 64-thread block)
__global__ void k_scan_top(int nb, int n) {
    __shared__ int ws[2];
    const int tid = threadIdx.x, lane = tid & 31, wid = tid >> 5;
    int v = (tid < nb) ? g_bsum[tid] : 0;
    int inc = v;
#pragma unroll
    for (int o = 1; o < 32; o <<= 1) {
        int t = __shfl_up_sync(0xffffffffu, inc, o);
        if (lane >= o) inc += t;
    }
    if (lane == 31) ws[wid] = inc;
    __syncthreads();
    int excl = inc - v + ((wid == 1) ? ws[0] : 0);
    if (tid < nb) g_boff[tid] = excl;
    if (tid == nb - 1) g_roff[n] = excl + v;
}

// 3c) add block offsets -> final roff/cursor; fused dinv = rsqrt(deg)
__global__ void k_scan_add(int n) {
    int i = blockIdx.x * blockDim.x + threadIdx.x;
    if (i < n) {
        int r = g_roff[i] + g_boff[i >> 10];
        g_roff[i] = r;
        g_cursor[i] = r;
        g_dinv[i] = rsqrtf((float)g_deg[i]);
    }
}

// 4) CSR fill: adj[cursor[r]++] = c  (order within a row irrelevant: sum)
__global__ void k_fill(const int* __restrict__ ei, int E) {
    int i = blockIdx.x * blockDim.x + threadIdx.x;
    if (i < E) {
        int r = ei[i];
        int c = ei[E + i];
        int pos = atomicAdd(&g_cursor[r], 1);
        g_adj[pos] = c;
    }
}

// ---------------------------------------------------------------------------
// 5) xl = x @ W + b ; y = dinv * xl  (scratch only). BM=64, BN=128, BK=64.
__global__ __launch_bounds__(256) void k_gemm(const float* __restrict__ x,
                                              const float* __restrict__ Wm,
                                              const float* __restrict__ bias,
                                              int n) {
    __shared__ float w_s[64][D];   // 32 KB
    __shared__ float x_s[64][64];  // 16 KB

    const int tid  = threadIdx.x;
    const int tx   = tid & 31;     // col quad
    const int ty   = tid >> 5;     // row group
    const int row0 = blockIdx.x * 64;

    float acc[8][4];
#pragma unroll
    for (int i = 0; i < 8; i++)
#pragma unroll
        for (int j = 0; j < 4; j++) acc[i][j] = 0.0f;

    for (int kk = 0; kk < D; kk += 64) {
        {
            const float4* W4 = (const float4*)(Wm + (size_t)kk * D);
            float4* ws4 = (float4*)&w_s[0][0];
            for (int i = tid; i < 64 * (D / 4); i += 256) ws4[i] = W4[i];
        }
        {
            for (int i = tid; i < 64 * 16; i += 256) {
                int r = i >> 4, c4 = i & 15;
                float4 v = make_float4(0.f, 0.f, 0.f, 0.f);
                if (row0 + r < n)
                    v = *(const float4*)(x + (size_t)(row0 + r) * D + kk + c4 * 4);
                *(float4*)&x_s[r][c4 * 4] = v;
            }
        }
        __syncthreads();

#pragma unroll 4
        for (int k = 0; k < 64; k++) {
            float4 wv = ((const float4*)&w_s[k][0])[tx];
#pragma unroll
            for (int i = 0; i < 8; i++) {
                float xv = x_s[ty * 8 + i][k];
                acc[i][0] += xv * wv.x;
                acc[i][1] += xv * wv.y;
                acc[i][2] += xv * wv.z;
                acc[i][3] += xv * wv.w;
            }
        }
        __syncthreads();
    }

    float4 bv = ((const float4*)bias)[tx];
#pragma unroll
    for (int i = 0; i < 8; i++) {
        int row = row0 + ty * 8 + i;
        if (row < n) {
            float s = g_dinv[row];
            float4 v;
            v.x = (acc[i][0] + bv.x) * s;
            v.y = (acc[i][1] + bv.y) * s;
            v.z = (acc[i][2] + bv.z) * s;
            v.w = (acc[i][3] + bv.w) * s;
            *(float4*)(g_y + (size_t)row * D + tx * 4) = v;
        }
    }
}

// ---------------------------------------------------------------------------
// 6) gather: one warp per node, register accumulation, zero atomics.
//    out[r] = dinv[r] * ( y[r] + sum_{c in adj[r]} y[c] )
__global__ __launch_bounds__(256) void k_gather(float* __restrict__ out, int n) {
    const int node = blockIdx.x * 8 + (threadIdx.x >> 5);
    const int lane = threadIdx.x & 31;
    if (node >= n) return;

    const float4* __restrict__ y4 = (const float4*)g_y;

    float4 a0 = y4[(size_t)node * 32 + lane];   // self-loop term
    float4 a1 = make_float4(0.f, 0.f, 0.f, 0.f);

    const int s = g_roff[node];
    const int e = g_roff[node + 1];

    for (int j = s; j < e; j += 32) {
        int cid = 0;
        if (j + lane < e) cid = g_adj[j + lane];
        const int cnt = min(32, e - j);
        int t = 0;
        for (; t + 4 <= cnt; t += 4) {
            int c0 = __shfl_sync(0xffffffffu, cid, t + 0);
            int c1 = __shfl_sync(0xffffffffu, cid, t + 1);
            int c2 = __shfl_sync(0xffffffffu, cid, t + 2);
            int c3 = __shfl_sync(0xffffffffu, cid, t + 3);
            float4 v0 = y4[(size_t)c0 * 32 + lane];
            float4 v1 = y4[(size_t)c1 * 32 + lane];
            float4 v2 = y4[(size_t)c2 * 32 + lane];
            float4 v3 = y4[(size_t)c3 * 32 + lane];
            a0.x += v0.x; a0.y += v0.y; a0.z += v0.z; a0.w += v0.w;
            a1.x += v1.x; a1.y += v1.y; a1.z += v1.z; a1.w += v1.w;
            a0.x += v2.x; a0.y += v2.y; a0.z += v2.z; a0.w += v2.w;
            a1.x += v3.x; a1.y += v3.y; a1.z += v3.z; a1.w += v3.w;
        }
        for (; t < cnt; t++) {
            int c = __shfl_sync(0xffffffffu, cid, t);
            float4 v = y4[(size_t)c * 32 + lane];
            a0.x += v.x; a0.y += v.y; a0.z += v.z; a0.w += v.w;
        }
    }

    const float sd = g_dinv[node];
    float4 r;
    r.x = (a0.x + a1.x) * sd;
    r.y = (a0.y + a1.y) * sd;
    r.z = (a0.z + a1.z) * sd;
    r.w = (a0.w + a1.w) * sd;
    ((float4*)out)[(size_t)node * 32 + lane] = r;
}

// ---------------------------------------------------------------------------
extern "C" void kernel_launch(void* const* d_in, const int* in_sizes, int n_in,
                              void* d_out, int out_size) {
    const float* x  = (const float*)d_in[0];
    const int*   ei = (const int*)d_in[1];    // int32 (JAX canonicalized)
    const float* Wm = (const float*)d_in[2];
    const float* b  = (const float*)d_in[3];
    float* out = (float*)d_out;

    const int n = in_sizes[0] / D;       // 50000
    const int E = in_sizes[1] / 2;       // 1,600,000

    const int nb = (n + 1023) / 1024;    // 49 scan blocks

    k_init    <<<(n + 255) / 256, 256>>>(n);
    k_hist    <<<(E + 255) / 256, 256>>>(ei, E);
    k_scan_blk<<<nb, 1024>>>(n);
    k_scan_top<<<1, 64>>>(nb, n);
    k_scan_add<<<(n + 255) / 256, 256>>>(n);
    k_fill    <<<(E + 255) / 256, 256>>>(ei, E);
    k_gemm    <<<(n + 63) / 64, 256>>>(x, Wm, b, n);
    k_gather  <<<(n + 7) / 8, 256>>>(out, n);
}

// round 11
// speedup vs baseline: 1.6504x; 1.1427x over previous
#include <cuda_runtime.h>
#include <cuda_fp16.h>
#include <cstdint>

#define D 128
#define N_MAX 50048
#define E_MAX 1600512
#define NB_MAX 64   // max scan blocks (ceil(50000/1024)=49)

// Scratch (device globals: allocation-free per harness rules)
__device__ int     g_deg[N_MAX];
__device__ int     g_rowcnt[N_MAX];
__device__ int     g_roff[N_MAX + 1];
__device__ int     g_cursor[N_MAX];
__device__ int     g_bsum[NB_MAX];
__device__ int     g_boff[NB_MAX];
__device__ int     g_adj[E_MAX];
__device__ float   g_dinv[N_MAX];
__device__ __half2 g_yh[(size_t)N_MAX * (D / 2)];  // y in fp16: halves gather L2 traffic

// ---------------------------------------------------------------------------
// 1) init: self-loop degree 1, row counters 0
__global__ void k_init(int n) {
    int i = blockIdx.x * blockDim.x + threadIdx.x;
    if (i < n) { g_deg[i] = 1; g_rowcnt[i] = 0; }
}

// 2) fused histogram: degree over col, CSR counts over row (one pass over ei)
__global__ void k_hist(const int* __restrict__ ei, int E) {
    int i = blockIdx.x * blockDim.x + threadIdx.x;
    if (i < E) {
        int r = ei[i];
        int c = ei[E + i];
        atomicAdd(&g_deg[c], 1);
        atomicAdd(&g_rowcnt[r], 1);
    }
}

// ---------------------------------------------------------------------------
// 3a) per-block exclusive scan of 1024-element chunks + block sums
__global__ __launch_bounds__(1024) void k_scan_blk(int n) {
    __shared__ int warp_sums[32];
    const int tid = threadIdx.x, lane = tid & 31, wid = tid >> 5;
    const int i = blockIdx.x * 1024 + tid;

    int v = (i < n) ? g_rowcnt[i] : 0;
    int inc = v;
#pragma unroll
    for (int o = 1; o < 32; o <<= 1) {
        int t = __shfl_up_sync(0xffffffffu, inc, o);
        if (lane >= o) inc += t;
    }
    if (lane == 31) warp_sums[wid] = inc;
    __syncthreads();
    if (wid == 0) {
        int ws = warp_sums[lane];
#pragma unroll
        for (int o = 1; o < 32; o <<= 1) {
            int t = __shfl_up_sync(0xffffffffu, ws, o);
            if (lane >= o) ws += t;
        }
        warp_sums[lane] = ws;
    }
    __syncthreads();
    int excl = ((wid == 0) ? 0 : warp_sums[wid - 1]) + inc - v;
    if (i < n) g_roff[i] = excl;
    if (tid == 0) g_bsum[blockIdx.x] = warp_sums[31];
}

// 3b) scan the block sums (nb <= 64, one 64-thread block)
__global__ void k_scan_top(int nb, int n) {
    __shared__ int ws[2];
    const int tid = threadIdx.x, lane = tid & 31, wid = tid >> 5;
    int v = (tid < nb) ? g_bsum[tid] : 0;
    int inc = v;
#pragma unroll
    for (int o = 1; o < 32; o <<= 1) {
        int t = __shfl_up_sync(0xffffffffu, inc, o);
        if (lane >= o) inc += t;
    }
    if (lane == 31) ws[wid] = inc;
    __syncthreads();
    int excl = inc - v + ((wid == 1) ? ws[0] : 0);
    if (tid < nb) g_boff[tid] = excl;
    if (tid == nb - 1) g_roff[n] = excl + v;
}

// 3c) add block offsets -> final roff/cursor; fused dinv = rsqrt(deg)
__global__ void k_scan_add(int n) {
    int i = blockIdx.x * blockDim.x + threadIdx.x;
    if (i < n) {
        int r = g_roff[i] + g_boff[i >> 10];
        g_roff[i] = r;
        g_cursor[i] = r;
        g_dinv[i] = rsqrtf((float)g_deg[i]);
    }
}

// 4) CSR fill: adj[cursor[r]++] = c  (order within a row irrelevant: sum)
__global__ void k_fill(const int* __restrict__ ei, int E) {
    int i = blockIdx.x * blockDim.x + threadIdx.x;
    if (i < E) {
        int r = ei[i];
        int c = ei[E + i];
        int pos = atomicAdd(&g_cursor[r], 1);
        g_adj[pos] = c;
    }
}

// ---------------------------------------------------------------------------
// 5) xl = x @ W + b ; y = dinv * xl stored as fp16. BM=64, BN=128, BK=64.
__global__ __launch_bounds__(256) void k_gemm(const float* __restrict__ x,
                                              const float* __restrict__ Wm,
                                              const float* __restrict__ bias,
                                              int n) {
    __shared__ float w_s[64][D];   // 32 KB
    __shared__ float x_s[64][64];  // 16 KB

    const int tid  = threadIdx.x;
    const int tx   = tid & 31;     // col quad
    const int ty   = tid >> 5;     // row group
    const int row0 = blockIdx.x * 64;

    float acc[8][4];
#pragma unroll
    for (int i = 0; i < 8; i++)
#pragma unroll
        for (int j = 0; j < 4; j++) acc[i][j] = 0.0f;

    for (int kk = 0; kk < D; kk += 64) {
        {
            const float4* W4 = (const float4*)(Wm + (size_t)kk * D);
            float4* ws4 = (float4*)&w_s[0][0];
            for (int i = tid; i < 64 * (D / 4); i += 256) ws4[i] = W4[i];
        }
        {
            for (int i = tid; i < 64 * 16; i += 256) {
                int r = i >> 4, c4 = i & 15;
                float4 v = make_float4(0.f, 0.f, 0.f, 0.f);
                if (row0 + r < n)
                    v = *(const float4*)(x + (size_t)(row0 + r) * D + kk + c4 * 4);
                *(float4*)&x_s[r][c4 * 4] = v;
            }
        }
        __syncthreads();

#pragma unroll 4
        for (int k = 0; k < 64; k++) {
            float4 wv = ((const float4*)&w_s[k][0])[tx];
#pragma unroll
            for (int i = 0; i < 8; i++) {
                float xv = x_s[ty * 8 + i][k];
                acc[i][0] += xv * wv.x;
                acc[i][1] += xv * wv.y;
                acc[i][2] += xv * wv.z;
                acc[i][3] += xv * wv.w;
            }
        }
        __syncthreads();
    }

    float4 bv = ((const float4*)bias)[tx];
#pragma unroll
    for (int i = 0; i < 8; i++) {
        int row = row0 + ty * 8 + i;
        if (row < n) {
            float s = g_dinv[row];
            __half2 h0 = __floats2half2_rn((acc[i][0] + bv.x) * s,
                                           (acc[i][1] + bv.y) * s);
            __half2 h1 = __floats2half2_rn((acc[i][2] + bv.z) * s,
                                           (acc[i][3] + bv.w) * s);
            uint2 u;
            u.x = *(unsigned int*)&h0;
            u.y = *(unsigned int*)&h1;
            // uint2 index: row*32 + tx covers half columns 4*tx .. 4*tx+3
            ((uint2*)g_yh)[(size_t)row * 32 + tx] = u;
        }
    }
}

// ---------------------------------------------------------------------------
// 6) gather: one warp per node, fp16 loads, fp32 register accumulation.
//    out[r] = dinv[r] * ( y[r] + sum_{c in adj[r]} y[c] )
__global__ __launch_bounds__(256) void k_gather(float* __restrict__ out, int n) {
    const int node = blockIdx.x * 8 + (threadIdx.x >> 5);
    const int lane = threadIdx.x & 31;
    if (node >= n) return;

    const uint2* __restrict__ y2 = (const uint2*)g_yh;  // node*32 + lane

    float4 a0, a1 = make_float4(0.f, 0.f, 0.f, 0.f);
    {   // self-loop term
        uint2 u = y2[(size_t)node * 32 + lane];
        float2 f0 = __half22float2(*(__half2*)&u.x);
        float2 f1 = __half22float2(*(__half2*)&u.y);
        a0 = make_float4(f0.x, f0.y, f1.x, f1.y);
    }

    const int s = g_roff[node];
    const int e = g_roff[node + 1];

    for (int j = s; j < e; j += 32) {
        int cid = 0;
        if (j + lane < e) cid = g_adj[j + lane];
        const int cnt = min(32, e - j);
        int t = 0;
        for (; t + 4 <= cnt; t += 4) {
            int c0 = __shfl_sync(0xffffffffu, cid, t + 0);
            int c1 = __shfl_sync(0xffffffffu, cid, t + 1);
            int c2 = __shfl_sync(0xffffffffu, cid, t + 2);
            int c3 = __shfl_sync(0xffffffffu, cid, t + 3);
            uint2 u0 = y2[(size_t)c0 * 32 + lane];
            uint2 u1 = y2[(size_t)c1 * 32 + lane];
            uint2 u2 = y2[(size_t)c2 * 32 + lane];
            uint2 u3 = y2[(size_t)c3 * 32 + lane];
            float2 f;
            f = __half22float2(*(__half2*)&u0.x); a0.x += f.x; a0.y += f.y;
            f = __half22float2(*(__half2*)&u0.y); a0.z += f.x; a0.w += f.y;
            f = __half22float2(*(__half2*)&u1.x); a1.x += f.x; a1.y += f.y;
            f = __half22float2(*(__half2*)&u1.y); a1.z += f.x; a1.w += f.y;
            f = __half22float2(*(__half2*)&u2.x); a0.x += f.x; a0.y += f.y;
            f = __half22float2(*(__half2*)&u2.y); a0.z += f.x; a0.w += f.y;
            f = __half22float2(*(__half2*)&u3.x); a1.x += f.x; a1.y += f.y;
            f = __half22float2(*(__half2*)&u3.y); a1.z += f.x; a1.w += f.y;
        }
        for (; t < cnt; t++) {
            int c = __shfl_sync(0xffffffffu, cid, t);
            uint2 u = y2[(size_t)c * 32 + lane];
            float2 f;
            f = __half22float2(*(__half2*)&u.x); a0.x += f.x; a0.y += f.y;
            f = __half22float2(*(__half2*)&u.y); a0.z += f.x; a0.w += f.y;
        }
    }

    const float sd = g_dinv[node];
    float4 r;
    r.x = (a0.x + a1.x) * sd;
    r.y = (a0.y + a1.y) * sd;
    r.z = (a0.z + a1.z) * sd;
    r.w = (a0.w + a1.w) * sd;
    ((float4*)out)[(size_t)node * 32 + lane] = r;
}

// ---------------------------------------------------------------------------
extern "C" void kernel_launch(void* const* d_in, const int* in_sizes, int n_in,
                              void* d_out, int out_size) {
    const float* x  = (const float*)d_in[0];
    const int*   ei = (const int*)d_in[1];    // int32 (JAX canonicalized)
    const float* Wm = (const float*)d_in[2];
    const float* b  = (const float*)d_in[3];
    float* out = (float*)d_out;

    const int n = in_sizes[0] / D;       // 50000
    const int E = in_sizes[1] / 2;       // 1,600,000

    const int nb = (n + 1023) / 1024;    // 49 scan blocks

    k_init    <<<(n + 255) / 256, 256>>>(n);
    k_hist    <<<(E + 255) / 256, 256>>>(ei, E);
    k_scan_blk<<<nb, 1024>>>(n);
    k_scan_top<<<1, 64>>>(nb, n);
    k_scan_add<<<(n + 255) / 256, 256>>>(n);
    k_fill    <<<(E + 255) / 256, 256>>>(ei, E);
    k_gemm    <<<(n + 63) / 64, 256>>>(x, Wm, b, n);
    k_gather  <<<(n + 7) / 8, 256>>>(out, n);
}